// round 8
// baseline (speedup 1.0000x reference)
#include <cuda_runtime.h>
#include <cuda_fp16.h>
#include <cstdint>

// Problem constants (B=64, S=1024, D=768, R=4)
#define DD    768
#define ND    2304
#define RR    4
#define MTOT  65536

// GEMM tiling
#define BM 128
#define BN 128
#define BK 32
#define NKT (DD / BK)        // 24
#define STAGES 3

// smem stage layout:
//   A: fp32, 128 rows x 32 floats, padded to 160 B/row  -> 20480 B
//   B: fp16, 128 rows x 32 halves, padded to 80 B/row   -> 10240 B
#define AROWB  160
#define BROWB  80
#define A_T    0
#define B_T    (128 * AROWB)            // 20480
#define STG    (128 * AROWB + 128 * BROWB)  // 30720
#define SMEM_TOTAL (STAGES * STG)       // 92160

// Static device scratch (no runtime allocation allowed)
__device__ __align__(128) __half g_W[(size_t)ND * DD];

// ---------------------------------------------------------------------------
// PTX helpers (baseline ISA only — safe under compute_103 virtual arch)
// ---------------------------------------------------------------------------
__device__ __forceinline__ uint32_t smem_u32(const void* p) {
    uint32_t a;
    asm("{ .reg .u64 t; cvta.to.shared.u64 t, %1; cvt.u32.u64 %0, t; }"
        : "=r"(a) : "l"(p));
    return a;
}

#define CPA(saddr, gaddr) \
    asm volatile("cp.async.cg.shared.global [%0], [%1], 16;" \
                 :: "r"(saddr), "l"(gaddr))

#define CP_COMMIT() asm volatile("cp.async.commit_group;" ::: "memory")
#define CP_WAIT1()  asm volatile("cp.async.wait_group 1;" ::: "memory")

#define LDSM4(r, addr)                                                        \
    asm volatile("ldmatrix.sync.aligned.m8n8.x4.shared.b16 {%0,%1,%2,%3}, [%4];" \
                 : "=r"((r)[0]), "=r"((r)[1]), "=r"((r)[2]), "=r"((r)[3])     \
                 : "r"(addr))

// load 2 consecutive fp32 from smem, convert to packed f16x2 (lo=first)
#define LDS_CVT(dreg, addr) do {                                              \
    float _f0, _f1;                                                           \
    asm volatile("ld.shared.v2.f32 {%0,%1}, [%2];"                            \
                 : "=f"(_f0), "=f"(_f1) : "r"(addr));                         \
    asm("cvt.rn.f16x2.f32 %0, %1, %2;" : "=r"(dreg) : "f"(_f1), "f"(_f0));    \
} while (0)

#define MMA(c, a, b0, b1)                                                     \
    asm volatile("mma.sync.aligned.m16n8k16.row.col.f32.f16.f16.f32 "         \
                 "{%0,%1,%2,%3},{%4,%5,%6,%7},{%8,%9},{%0,%1,%2,%3};"         \
                 : "+f"((c)[0]), "+f"((c)[1]), "+f"((c)[2]), "+f"((c)[3])     \
                 : "r"((a)[0]), "r"((a)[1]), "r"((a)[2]), "r"((a)[3]),        \
                   "r"(b0), "r"(b1))

// ---------------------------------------------------------------------------
// Kernel 0: fold LoRA into W (rank-4 update on q and v row blocks) -> fp16
// ---------------------------------------------------------------------------
__global__ void fold_w(const float* __restrict__ W,
                       const float* __restrict__ Aq, const float* __restrict__ Bq,
                       const float* __restrict__ Av, const float* __restrict__ Bv,
                       const float* __restrict__ s0p) {
    int idx = blockIdx.x * blockDim.x + threadIdx.x;
    if (idx >= ND * DD) return;
    int e = idx / DD;
    int d = idx - e * DD;
    float v = W[idx];
    float s = s0p[0];
    if (e < DD) {
        float acc = 0.f;
#pragma unroll
        for (int r = 0; r < RR; r++) acc = fmaf(Bq[e * RR + r], Aq[r * DD + d], acc);
        v = fmaf(s, acc, v);
    } else if (e >= 2 * DD) {
        int e2 = e - 2 * DD;
        float acc = 0.f;
#pragma unroll
        for (int r = 0; r < RR; r++) acc = fmaf(Bv[e2 * RR + r], Av[r * DD + d], acc);
        v = fmaf(s, acc, v);
    }
    g_W[idx] = __float2half(v);
}

// ---------------------------------------------------------------------------
// Kernel 1: fp16 mma.sync GEMM, fp32 accumulate, in-loop X conversion.
//   Out[M, ND] = half(X) @ W^T + bias
//   A loaded as fp32 tiles (cp.async), fragments built by LDS.64 + CVT.
//   128x128x32 CTA tile, 8 warps (2x4), 64x32 warp tile, 3-stage pipeline.
//   2 CTAs/SM (90 KB smem each).
// ---------------------------------------------------------------------------
__global__ void __launch_bounds__(256, 2) gemm_mma(
    const float* __restrict__ X,
    const float* __restrict__ bias, float* __restrict__ Out) {
    extern __shared__ char smem[];
    const uint32_t sb = smem_u32(smem);

    const int tid  = threadIdx.x;
    const int wid  = tid >> 5;
    const int lane = tid & 31;
    const int wm   = wid >> 2;          // 0..1  (64 rows each)
    const int wn   = wid & 3;           // 0..3  (32 cols each)
    const int n0   = blockIdx.x * BN;
    const int m0   = blockIdx.y * BM;

    // A loader: 1024 16B chunks (128 rows x 8), 4 per thread
    const int ar = tid >> 1;            // base row pair index helper
    // B loader: 512 16B chunks, 2 per thread
    const int br0 = tid >> 2;           // 0..63
    const int bcc = tid & 3;

    float acc[4][4][4];
#pragma unroll
    for (int i = 0; i < 4; i++)
#pragma unroll
        for (int j = 0; j < 4; j++)
#pragma unroll
            for (int q = 0; q < 4; q++) acc[i][j][q] = 0.f;

    // ---- stage loader ----
    auto load_stage = [&](int kt, int buf) {
        const uint32_t st = sb + buf * STG;
        // A: fp32, chunk id = tid + i*256 ; row = id>>3, c16 = id&7
#pragma unroll
        for (int i = 0; i < 4; i++) {
            const int id  = tid + i * 256;
            const int row = id >> 3;
            const int c16 = id & 7;
            const uint32_t so = st + A_T + row * AROWB + c16 * 16;
            const size_t g = (size_t)(m0 + row) * DD + kt * BK + c16 * 4;
            CPA(so, (const char*)(X + g));
        }
        // B: fp16
#pragma unroll
        for (int i = 0; i < 2; i++) {
            const int row = br0 + i * 64;
            const uint32_t so = st + B_T + row * BROWB + bcc * 16;
            const size_t g = (size_t)(n0 + row) * DD + kt * BK + bcc * 8;
            CPA(so, (const char*)(g_W + g));
        }
    };

    load_stage(0, 0); CP_COMMIT();
    load_stage(1, 1); CP_COMMIT();

    // per-lane fragment address pieces
    const int gq = lane >> 2;           // 0..7  (row within 8-row group)
    const int tq = lane & 3;            // 0..3  (column pair)
    const int lrow = lane & 15;
    const int lhal = (lane >> 4) << 4;

    for (int kt = 0; kt < NKT; kt++) {
        const int buf = kt % STAGES;
        CP_WAIT1();
        __syncthreads();
        if (kt + 2 < NKT) load_stage(kt + 2, (kt + 2) % STAGES);
        CP_COMMIT();

        const uint32_t st = sb + buf * STG;
        // A fragment base: row = wm*64 + ti*16 + gq (+8), col = kk*16 + 2*tq (+8)
        const uint32_t abase = st + A_T + (wm * 64 + gq) * AROWB + tq * 8;
        const uint32_t bbase = st + B_T + (wn * 32 + lrow) * BROWB + lhal;

#pragma unroll
        for (int kk = 0; kk < 2; kk++) {
            uint32_t aw[4][4], bw[2][4];
            const uint32_t ak = abase + kk * 64;     // kk*16 floats
#pragma unroll
            for (int ti = 0; ti < 4; ti++) {
                const uint32_t at = ak + ti * (16 * AROWB);
                LDS_CVT(aw[ti][0], at);
                LDS_CVT(aw[ti][1], at + 8 * AROWB);
                LDS_CVT(aw[ti][2], at + 32);          // +8 cols
                LDS_CVT(aw[ti][3], at + 8 * AROWB + 32);
            }
#pragma unroll
            for (int tj = 0; tj < 2; tj++)
                LDSM4(bw[tj], bbase + tj * (16 * BROWB) + kk * 32);
#pragma unroll
            for (int ti = 0; ti < 4; ti++) {
#pragma unroll
                for (int nj = 0; nj < 4; nj++) {
                    const int tj = nj >> 1, o = nj & 1;
                    MMA(acc[ti][nj], aw[ti], bw[tj][o], bw[tj][o + 2]);
                }
            }
        }
        __syncthreads();
    }

    // ---- epilogue: bias + store ----
    const int orow_base = m0 + wm * 64 + (lane >> 2);
    const int ocol_base = n0 + wn * 32 + (lane & 3) * 2;
#pragma unroll
    for (int ti = 0; ti < 4; ti++) {
        const int r0 = orow_base + ti * 16;
#pragma unroll
        for (int nj = 0; nj < 4; nj++) {
            const int c = ocol_base + nj * 8;
            const float2 bs = *reinterpret_cast<const float2*>(bias + c);
            float2 v0, v1;
            v0.x = acc[ti][nj][0] + bs.x;
            v0.y = acc[ti][nj][1] + bs.y;
            v1.x = acc[ti][nj][2] + bs.x;
            v1.y = acc[ti][nj][3] + bs.y;
            *reinterpret_cast<float2*>(Out + (size_t)r0 * ND + c) = v0;
            *reinterpret_cast<float2*>(Out + (size_t)(r0 + 8) * ND + c) = v1;
        }
    }
}

// ---------------------------------------------------------------------------
// Launch.  Inputs (metadata order): x, W_qkv, b_qkv, A_q, B_q, A_v, B_v, s0
// ---------------------------------------------------------------------------
extern "C" void kernel_launch(void* const* d_in, const int* in_sizes, int n_in,
                              void* d_out, int out_size) {
    const float* x  = (const float*)d_in[0];
    const float* W  = (const float*)d_in[1];
    const float* b  = (const float*)d_in[2];
    const float* Aq = (const float*)d_in[3];
    const float* Bq = (const float*)d_in[4];
    const float* Av = (const float*)d_in[5];
    const float* Bv = (const float*)d_in[6];
    const float* s0 = (const float*)d_in[7];
    float* out = (float*)d_out;

    fold_w<<<(ND * DD + 255) / 256, 256>>>(W, Aq, Bq, Av, Bv, s0);

    static bool attr_set = false;
    if (!attr_set) {
        cudaFuncSetAttribute(gemm_mma,
                             cudaFuncAttributeMaxDynamicSharedMemorySize,
                             SMEM_TOTAL);
        attr_set = true;
    }
    dim3 grid(ND / BN, MTOT / BM);      // (18, 512); x-fast => X tile L2 reuse
    gemm_mma<<<grid, 256, SMEM_TOTAL>>>(x, b, out);
}

// round 9
// speedup vs baseline: 1.4690x; 1.4690x over previous
#include <cuda_runtime.h>
#include <cuda_fp16.h>
#include <cstdint>

// Problem constants (B=64, S=1024, D=768, R=4)
#define DD    768
#define ND    2304
#define RR    4
#define MTOT  65536

// GEMM tiling
#define BM 128
#define BN 128
#define BK 32
#define NKT (DD / BK)        // 24

// smem layout (per CTA):
//   A32 ring: 3 stages of fp32 128x32, rows padded to 144 B  -> 3 * 18432
//   B   ring: 3 stages of fp16 128x32, rows padded to 80 B   -> 3 * 10240
//   A16 bufs: 2 buffers of fp16 128x32, rows padded to 80 B  -> 2 * 10240
#define A32ROWB 144
#define A16ROWB 80
#define BROWB   80
#define A32_TB  (128 * A32ROWB)   // 18432
#define B_TB    (128 * BROWB)     // 10240
#define A16_TB  (128 * A16ROWB)   // 10240
#define OFF_A32(s) ((s) * A32_TB)
#define OFF_B(s)   (3 * A32_TB + (s) * B_TB)
#define OFF_A16(p) (3 * A32_TB + 3 * B_TB + (p) * A16_TB)
#define SMEM_TOTAL (3 * A32_TB + 3 * B_TB + 2 * A16_TB)   // 106496 -> 2 CTAs/SM

// Static device scratch (no runtime allocation allowed)
__device__ __align__(128) __half g_W[(size_t)ND * DD];

// ---------------------------------------------------------------------------
// PTX helpers (baseline ISA only — safe under compute_103 virtual arch)
// ---------------------------------------------------------------------------
__device__ __forceinline__ uint32_t smem_u32(const void* p) {
    uint32_t a;
    asm("{ .reg .u64 t; cvta.to.shared.u64 t, %1; cvt.u32.u64 %0, t; }"
        : "=r"(a) : "l"(p));
    return a;
}

#define CPA(saddr, gaddr) \
    asm volatile("cp.async.cg.shared.global [%0], [%1], 16;" \
                 :: "r"(saddr), "l"(gaddr))

#define CP_COMMIT() asm volatile("cp.async.commit_group;" ::: "memory")
#define CP_WAIT0()  asm volatile("cp.async.wait_group 0;" ::: "memory")
#define CP_WAIT1()  asm volatile("cp.async.wait_group 1;" ::: "memory")

#define LDSM4(r, addr)                                                        \
    asm volatile("ldmatrix.sync.aligned.m8n8.x4.shared.b16 {%0,%1,%2,%3}, [%4];" \
                 : "=r"((r)[0]), "=r"((r)[1]), "=r"((r)[2]), "=r"((r)[3])     \
                 : "r"(addr))

#define MMA(c, a, b0, b1)                                                     \
    asm volatile("mma.sync.aligned.m16n8k16.row.col.f32.f16.f16.f32 "         \
                 "{%0,%1,%2,%3},{%4,%5,%6,%7},{%8,%9},{%0,%1,%2,%3};"         \
                 : "+f"((c)[0]), "+f"((c)[1]), "+f"((c)[2]), "+f"((c)[3])     \
                 : "r"((a)[0]), "r"((a)[1]), "r"((a)[2]), "r"((a)[3]),        \
                   "r"(b0), "r"(b1))

// ---------------------------------------------------------------------------
// Kernel 0: fold LoRA into W (rank-4 update on q and v row blocks) -> fp16
// ---------------------------------------------------------------------------
__global__ void fold_w(const float* __restrict__ W,
                       const float* __restrict__ Aq, const float* __restrict__ Bq,
                       const float* __restrict__ Av, const float* __restrict__ Bv,
                       const float* __restrict__ s0p) {
    int idx = blockIdx.x * blockDim.x + threadIdx.x;
    if (idx >= ND * DD) return;
    int e = idx / DD;
    int d = idx - e * DD;
    float v = W[idx];
    float s = s0p[0];
    if (e < DD) {
        float acc = 0.f;
#pragma unroll
        for (int r = 0; r < RR; r++) acc = fmaf(Bq[e * RR + r], Aq[r * DD + d], acc);
        v = fmaf(s, acc, v);
    } else if (e >= 2 * DD) {
        int e2 = e - 2 * DD;
        float acc = 0.f;
#pragma unroll
        for (int r = 0; r < RR; r++) acc = fmaf(Bv[e2 * RR + r], Av[r * DD + d], acc);
        v = fmaf(s, acc, v);
    }
    g_W[idx] = __float2half(v);
}

// ---------------------------------------------------------------------------
// Kernel 1: fp16 mma.sync GEMM, fp32 accumulate; X converted in-kernel by a
//           bulk staged convert (fp32 smem -> fp16 smem), one iter ahead.
//   Out[M, ND] = half(X) @ W^T + bias
//   128x128x32 CTA tile, 8 warps (2x4), 64x32 warp tile. 2 CTAs/SM.
// ---------------------------------------------------------------------------
__global__ void __launch_bounds__(256, 2) gemm_mma(
    const float* __restrict__ X,
    const float* __restrict__ bias, float* __restrict__ Out) {
    extern __shared__ char smem[];
    const uint32_t sb = smem_u32(smem);

    const int tid  = threadIdx.x;
    const int wid  = tid >> 5;
    const int lane = tid & 31;
    const int wm   = wid >> 2;          // 0..1  (64 rows each)
    const int wn   = wid & 3;           // 0..3  (32 cols each)
    const int n0   = blockIdx.x * BN;
    const int m0   = blockIdx.y * BM;

    // B loader mapping: 512 16B chunks, 2 per thread
    const int br0 = tid >> 2;           // 0..63
    const int bcc = tid & 3;
    // convert mapping: 16 consecutive floats per thread
    const int cr = tid & 127;           // row
    const int ch = tid >> 7;            // half (cols 0-15 / 16-31)

    float acc[4][4][4];
#pragma unroll
    for (int i = 0; i < 4; i++)
#pragma unroll
        for (int j = 0; j < 4; j++)
#pragma unroll
            for (int q = 0; q < 4; q++) acc[i][j][q] = 0.f;

    // ---- stage loader: A fp32 + B fp16 into ring slot ----
    auto load_stage = [&](int kt, int s) {
        const uint32_t sa = sb + OFF_A32(s);
        // A32: 1024 16B chunks (128 rows x 8), 4 per thread
#pragma unroll
        for (int i = 0; i < 4; i++) {
            const int id  = tid + i * 256;
            const int row = id >> 3;
            const int c16 = id & 7;
            CPA(sa + row * A32ROWB + c16 * 16,
                (const char*)(X + (size_t)(m0 + row) * DD + kt * BK + c16 * 4));
        }
        const uint32_t sB = sb + OFF_B(s);
#pragma unroll
        for (int i = 0; i < 2; i++) {
            const int row = br0 + i * 64;
            CPA(sB + row * BROWB + bcc * 16,
                (const char*)(g_W + (size_t)(n0 + row) * DD + kt * BK + bcc * 8));
        }
    };

    // ---- bulk convert: A32[s] -> A16[p], 16 floats per thread ----
    auto convert = [&](int kt) {
        const int s = kt % 3, p = kt & 1;
        const float4* s32 = reinterpret_cast<const float4*>(
            smem + OFF_A32(s) + cr * A32ROWB + ch * 64);
        float4 f0 = s32[0], f1 = s32[1], f2 = s32[2], f3 = s32[3];
        __half2 h[8];
        h[0] = __floats2half2_rn(f0.x, f0.y);
        h[1] = __floats2half2_rn(f0.z, f0.w);
        h[2] = __floats2half2_rn(f1.x, f1.y);
        h[3] = __floats2half2_rn(f1.z, f1.w);
        h[4] = __floats2half2_rn(f2.x, f2.y);
        h[5] = __floats2half2_rn(f2.z, f2.w);
        h[6] = __floats2half2_rn(f3.x, f3.y);
        h[7] = __floats2half2_rn(f3.z, f3.w);
        uint4* s16 = reinterpret_cast<uint4*>(
            smem + OFF_A16(p) + cr * A16ROWB + ch * 32);
        const uint32_t* hw = reinterpret_cast<const uint32_t*>(h);
        s16[0] = make_uint4(hw[0], hw[1], hw[2], hw[3]);
        s16[1] = make_uint4(hw[4], hw[5], hw[6], hw[7]);
    };

    // ---- prologue ----
    load_stage(0, 0); CP_COMMIT();
    load_stage(1, 1); CP_COMMIT();
    CP_WAIT1();                 // stage 0 arrived
    __syncthreads();
    convert(0);                 // A16 buf 0 ready after next barrier

    // per-lane ldmatrix address pieces
    const int lrow = lane & 15;
    const int lhal = (lane >> 4) << 4;  // 0 or 16 bytes (8-col half)

    for (int kt = 0; kt < NKT; kt++) {
        CP_WAIT0();             // stage kt+1 (newest committed) arrived
        __syncthreads();        // visibility; all prior ldmatrix/convert done
        if (kt + 2 < NKT) { load_stage(kt + 2, (kt + 2) % 3); CP_COMMIT(); }
        if (kt + 1 < NKT) convert(kt + 1);
        __syncthreads();        // A16[kt&1] from prev iter stays valid; conv visible

        const uint32_t abase = sb + OFF_A16(kt & 1)
                             + (wm * 64 + lrow) * A16ROWB + lhal;
        const uint32_t bbase = sb + OFF_B(kt % 3)
                             + (wn * 32 + lrow) * BROWB + lhal;

#pragma unroll
        for (int kk = 0; kk < 2; kk++) {
            uint32_t aw[4][4], bw[2][4];
#pragma unroll
            for (int ti = 0; ti < 4; ti++)
                LDSM4(aw[ti], abase + ti * (16 * A16ROWB) + kk * 32);
#pragma unroll
            for (int tj = 0; tj < 2; tj++)
                LDSM4(bw[tj], bbase + tj * (16 * BROWB) + kk * 32);
#pragma unroll
            for (int ti = 0; ti < 4; ti++) {
#pragma unroll
                for (int nj = 0; nj < 4; nj++) {
                    const int tj = nj >> 1, o = nj & 1;
                    MMA(acc[ti][nj], aw[ti], bw[tj][o], bw[tj][o + 2]);
                }
            }
        }
    }

    // ---- epilogue: bias + store ----
    const int orow_base = m0 + wm * 64 + (lane >> 2);
    const int ocol_base = n0 + wn * 32 + (lane & 3) * 2;
#pragma unroll
    for (int ti = 0; ti < 4; ti++) {
        const int r0 = orow_base + ti * 16;
#pragma unroll
        for (int nj = 0; nj < 4; nj++) {
            const int c = ocol_base + nj * 8;
            const float2 bs = *reinterpret_cast<const float2*>(bias + c);
            float2 v0, v1;
            v0.x = acc[ti][nj][0] + bs.x;
            v0.y = acc[ti][nj][1] + bs.y;
            v1.x = acc[ti][nj][2] + bs.x;
            v1.y = acc[ti][nj][3] + bs.y;
            *reinterpret_cast<float2*>(Out + (size_t)r0 * ND + c) = v0;
            *reinterpret_cast<float2*>(Out + (size_t)(r0 + 8) * ND + c) = v1;
        }
    }
}

// ---------------------------------------------------------------------------
// Launch.  Inputs (metadata order): x, W_qkv, b_qkv, A_q, B_q, A_v, B_v, s0
// ---------------------------------------------------------------------------
extern "C" void kernel_launch(void* const* d_in, const int* in_sizes, int n_in,
                              void* d_out, int out_size) {
    const float* x  = (const float*)d_in[0];
    const float* W  = (const float*)d_in[1];
    const float* b  = (const float*)d_in[2];
    const float* Aq = (const float*)d_in[3];
    const float* Bq = (const float*)d_in[4];
    const float* Av = (const float*)d_in[5];
    const float* Bv = (const float*)d_in[6];
    const float* s0 = (const float*)d_in[7];
    float* out = (float*)d_out;

    fold_w<<<(ND * DD + 255) / 256, 256>>>(W, Aq, Bq, Av, Bv, s0);

    static bool attr_set = false;
    if (!attr_set) {
        cudaFuncSetAttribute(gemm_mma,
                             cudaFuncAttributeMaxDynamicSharedMemorySize,
                             SMEM_TOTAL);
        attr_set = true;
    }
    dim3 grid(ND / BN, MTOT / BM);      // (18, 512); x-fast => X tile L2 reuse
    gemm_mma<<<grid, 256, SMEM_TOTAL>>>(x, b, out);
}

// round 10
// speedup vs baseline: 1.8154x; 1.2358x over previous
#include <cuda_runtime.h>
#include <cuda_fp16.h>
#include <cstdint>

// Problem constants (B=64, S=1024, D=768, R=4)
#define DD    768
#define ND    2304
#define RR    4
#define MTOT  65536

// GEMM tiling
#define BM 128
#define BN 128
#define BK 32
#define NKT (DD / BK)        // 24
#define STAGES 4

// smem stage layout: padded rows of 40 halves (80 B) for conflict-free ldmatrix
#define ROWB   80
#define MAT_B  (128 * ROWB)  // 10240 bytes per matrix tile
#define A_T    0
#define B_T    (MAT_B)
#define STG    (2 * MAT_B)   // 20480
#define SMEM_TOTAL (STAGES * STG)  // 81920

// fused prep kernel split
#define NCONV_BLK ((MTOT * DD / 4) / 256)   // 49152
#define NFOLD_BLK ((ND * DD + 255) / 256)   // 6912

// Static device scratch (no runtime allocation allowed)
__device__ __align__(128) __half g_X[(size_t)MTOT * DD];
__device__ __align__(128) __half g_W[(size_t)ND * DD];

// ---------------------------------------------------------------------------
// PTX helpers (baseline ISA only — safe under compute_103 virtual arch)
// ---------------------------------------------------------------------------
__device__ __forceinline__ uint32_t smem_u32(const void* p) {
    uint32_t a;
    asm("{ .reg .u64 t; cvta.to.shared.u64 t, %1; cvt.u32.u64 %0, t; }"
        : "=r"(a) : "l"(p));
    return a;
}

#define CPA(saddr, gaddr) \
    asm volatile("cp.async.cg.shared.global [%0], [%1], 16;" \
                 :: "r"(saddr), "l"(gaddr))

#define CP_COMMIT() asm volatile("cp.async.commit_group;" ::: "memory")
#define CP_WAIT2()  asm volatile("cp.async.wait_group 2;" ::: "memory")

#define LDSM4(r, addr)                                                        \
    asm volatile("ldmatrix.sync.aligned.m8n8.x4.shared.b16 {%0,%1,%2,%3}, [%4];" \
                 : "=r"((r)[0]), "=r"((r)[1]), "=r"((r)[2]), "=r"((r)[3])     \
                 : "r"(addr))

#define MMA(c, a, b0, b1)                                                     \
    asm volatile("mma.sync.aligned.m16n8k16.row.col.f32.f16.f16.f32 "         \
                 "{%0,%1,%2,%3},{%4,%5,%6,%7},{%8,%9},{%0,%1,%2,%3};"         \
                 : "+f"((c)[0]), "+f"((c)[1]), "+f"((c)[2]), "+f"((c)[3])     \
                 : "r"((a)[0]), "r"((a)[1]), "r"((a)[2]), "r"((a)[3]),        \
                   "r"(b0), "r"(b1))

// ---------------------------------------------------------------------------
// Kernel 0 (fused prep): blocks [0, NCONV_BLK): X fp32 -> fp16
//                        blocks [NCONV_BLK, +NFOLD_BLK): LoRA-fold W -> fp16
// ---------------------------------------------------------------------------
__global__ void prep(const float4* __restrict__ X,
                     const float* __restrict__ W,
                     const float* __restrict__ Aq, const float* __restrict__ Bq,
                     const float* __restrict__ Av, const float* __restrict__ Bv,
                     const float* __restrict__ s0p) {
    if (blockIdx.x < NCONV_BLK) {
        size_t i = (size_t)blockIdx.x * blockDim.x + threadIdx.x;
        float4 v = X[i];
        __half2* ph = reinterpret_cast<__half2*>(g_X) + i * 2;
        ph[0] = __floats2half2_rn(v.x, v.y);
        ph[1] = __floats2half2_rn(v.z, v.w);
    } else {
        int idx = (blockIdx.x - NCONV_BLK) * blockDim.x + threadIdx.x;
        if (idx >= ND * DD) return;
        int e = idx / DD;
        int d = idx - e * DD;
        float v = W[idx];
        float s = s0p[0];
        if (e < DD) {
            float acc = 0.f;
#pragma unroll
            for (int r = 0; r < RR; r++) acc = fmaf(Bq[e * RR + r], Aq[r * DD + d], acc);
            v = fmaf(s, acc, v);
        } else if (e >= 2 * DD) {
            int e2 = e - 2 * DD;
            float acc = 0.f;
#pragma unroll
            for (int r = 0; r < RR; r++) acc = fmaf(Bv[e2 * RR + r], Av[r * DD + d], acc);
            v = fmaf(s, acc, v);
        }
        g_W[idx] = __float2half(v);
    }
}

// ---------------------------------------------------------------------------
// Kernel 1: fp16 mma.sync GEMM, single term, fp32 accumulate.  (R6-exact)
//   Out[M, ND] = X @ W^T + bias
//   128x128x32 CTA tile, 8 warps (2x4), 64x32 warp tile, 4-stage cp.async.
//   2 CTAs/SM (80 KB smem each).
// ---------------------------------------------------------------------------
__global__ void __launch_bounds__(256, 2) gemm_mma(
    const float* __restrict__ bias, float* __restrict__ Out) {
    extern __shared__ char smem[];
    const uint32_t sb = smem_u32(smem);

    const int tid  = threadIdx.x;
    const int wid  = tid >> 5;
    const int lane = tid & 31;
    const int wm   = wid >> 2;          // 0..1  (64 rows each)
    const int wn   = wid & 3;           // 0..3  (32 cols each)
    const int n0   = blockIdx.x * BN;
    const int m0   = blockIdx.y * BM;

    // global load mapping: 512 16B chunks per matrix tile, 2 per thread
    const int r0c = tid >> 2;           // row for chunk 0 (0..63)
    const int cc  = tid & 3;            // 16B column (0..3)

    float acc[4][4][4];
#pragma unroll
    for (int i = 0; i < 4; i++)
#pragma unroll
        for (int j = 0; j < 4; j++)
#pragma unroll
            for (int q = 0; q < 4; q++) acc[i][j][q] = 0.f;

    // ---- stage loader ----
    auto load_stage = [&](int kt, int buf) {
        const uint32_t st = sb + buf * STG;
#pragma unroll
        for (int i = 0; i < 2; i++) {
            const int row = r0c + i * 64;
            const uint32_t so = st + row * ROWB + cc * 16;
            const size_t ga = (size_t)(m0 + row) * DD + kt * BK + cc * 8;
            const size_t gb = (size_t)(n0 + row) * DD + kt * BK + cc * 8;
            CPA(so + A_T, (const char*)(g_X + ga));
            CPA(so + B_T, (const char*)(g_W + gb));
        }
    };

    load_stage(0, 0); CP_COMMIT();
    load_stage(1, 1); CP_COMMIT();
    load_stage(2, 2); CP_COMMIT();

    // per-lane ldmatrix address pieces
    const int lrow = lane & 15;
    const int lhal = (lane >> 4) << 4;  // 0 or 16 bytes (8-col half)

    for (int kt = 0; kt < NKT; kt++) {
        const int buf = kt % STAGES;
        CP_WAIT2();
        __syncthreads();
        if (kt + 3 < NKT) load_stage(kt + 3, (kt + 3) % STAGES);
        CP_COMMIT();

        const uint32_t st = sb + buf * STG;
        const uint32_t abase = st + (wm * 64 + lrow) * ROWB + lhal;
        const uint32_t bbase = st + (wn * 32 + lrow) * ROWB + lhal;

#pragma unroll
        for (int kk = 0; kk < 2; kk++) {
            uint32_t aw[4][4], bw[2][4];
#pragma unroll
            for (int ti = 0; ti < 4; ti++)
                LDSM4(aw[ti], abase + A_T + ti * (16 * ROWB) + kk * 32);
#pragma unroll
            for (int tj = 0; tj < 2; tj++)
                LDSM4(bw[tj], bbase + B_T + tj * (16 * ROWB) + kk * 32);
#pragma unroll
            for (int ti = 0; ti < 4; ti++) {
#pragma unroll
                for (int nj = 0; nj < 4; nj++) {
                    const int tj = nj >> 1, o = nj & 1;
                    MMA(acc[ti][nj], aw[ti], bw[tj][o], bw[tj][o + 2]);
                }
            }
        }
        __syncthreads();
    }

    // ---- epilogue: bias + store ----
    const int orow_base = m0 + wm * 64 + (lane >> 2);
    const int ocol_base = n0 + wn * 32 + (lane & 3) * 2;
#pragma unroll
    for (int ti = 0; ti < 4; ti++) {
        const int r0 = orow_base + ti * 16;
#pragma unroll
        for (int nj = 0; nj < 4; nj++) {
            const int c = ocol_base + nj * 8;
            const float2 bs = *reinterpret_cast<const float2*>(bias + c);
            float2 v0, v1;
            v0.x = acc[ti][nj][0] + bs.x;
            v0.y = acc[ti][nj][1] + bs.y;
            v1.x = acc[ti][nj][2] + bs.x;
            v1.y = acc[ti][nj][3] + bs.y;
            *reinterpret_cast<float2*>(Out + (size_t)r0 * ND + c) = v0;
            *reinterpret_cast<float2*>(Out + (size_t)(r0 + 8) * ND + c) = v1;
        }
    }
}

// ---------------------------------------------------------------------------
// Launch.  Inputs (metadata order): x, W_qkv, b_qkv, A_q, B_q, A_v, B_v, s0
// ---------------------------------------------------------------------------
extern "C" void kernel_launch(void* const* d_in, const int* in_sizes, int n_in,
                              void* d_out, int out_size) {
    const float* x  = (const float*)d_in[0];
    const float* W  = (const float*)d_in[1];
    const float* b  = (const float*)d_in[2];
    const float* Aq = (const float*)d_in[3];
    const float* Bq = (const float*)d_in[4];
    const float* Av = (const float*)d_in[5];
    const float* Bv = (const float*)d_in[6];
    const float* s0 = (const float*)d_in[7];
    float* out = (float*)d_out;

    prep<<<NCONV_BLK + NFOLD_BLK, 256>>>((const float4*)x, W, Aq, Bq, Av, Bv, s0);

    static bool attr_set = false;
    if (!attr_set) {
        cudaFuncSetAttribute(gemm_mma,
                             cudaFuncAttributeMaxDynamicSharedMemorySize,
                             SMEM_TOTAL);
        attr_set = true;
    }
    dim3 grid(ND / BN, MTOT / BM);      // (18, 512); x-fast => X tile L2 reuse
    gemm_mma<<<grid, 256, SMEM_TOTAL>>>(b, out);
}

// round 13
// speedup vs baseline: 1.8816x; 1.0365x over previous
#include <cuda_runtime.h>
#include <cuda_fp16.h>
#include <cstdint>

// Problem constants (B=64, S=1024, D=768, R=4)
#define DD    768
#define ND    2304
#define RR    4
#define MTOT  65536

// GEMM tiling
#define BM 128
#define BN 128
#define BK 32
#define NKT (DD / BK)        // 24
#define STAGES 4

// smem stage layout: padded rows of 40 halves (80 B) for conflict-free ldmatrix
#define ROWB   80
#define MAT_B  (128 * ROWB)  // 10240 bytes per matrix tile
#define A_T    0
#define B_T    (MAT_B)
#define STG    (2 * MAT_B)   // 20480
#define SMEM_TOTAL (STAGES * STG)  // 81920

// fused prep kernel split
#define NCONV_BLK ((MTOT * DD / 4) / 256)   // 49152
#define NFOLD_BLK ((ND * DD + 255) / 256)   // 6912

// Static device scratch (no runtime allocation allowed)
__device__ __align__(128) __half g_X[(size_t)MTOT * DD];
__device__ __align__(128) __half g_W[(size_t)ND * DD];

// ---------------------------------------------------------------------------
// PTX helpers (baseline ISA only — safe under compute_103 virtual arch)
// ---------------------------------------------------------------------------
__device__ __forceinline__ uint32_t smem_u32(const void* p) {
    uint32_t a;
    asm("{ .reg .u64 t; cvta.to.shared.u64 t, %1; cvt.u32.u64 %0, t; }"
        : "=r"(a) : "l"(p));
    return a;
}

#define CPA(saddr, gaddr) \
    asm volatile("cp.async.cg.shared.global [%0], [%1], 16;" \
                 :: "r"(saddr), "l"(gaddr))

#define CP_COMMIT() asm volatile("cp.async.commit_group;" ::: "memory")
#define CP_WAIT2()  asm volatile("cp.async.wait_group 2;" ::: "memory")

#define LDSM4(r, addr)                                                        \
    asm volatile("ldmatrix.sync.aligned.m8n8.x4.shared.b16 {%0,%1,%2,%3}, [%4];" \
                 : "=r"((r)[0]), "=r"((r)[1]), "=r"((r)[2]), "=r"((r)[3])     \
                 : "r"(addr))

#define MMA(c, a, b0, b1)                                                     \
    asm volatile("mma.sync.aligned.m16n8k16.row.col.f32.f16.f16.f32 "         \
                 "{%0,%1,%2,%3},{%4,%5,%6,%7},{%8,%9},{%0,%1,%2,%3};"         \
                 : "+f"((c)[0]), "+f"((c)[1]), "+f"((c)[2]), "+f"((c)[3])     \
                 : "r"((a)[0]), "r"((a)[1]), "r"((a)[2]), "r"((a)[3]),        \
                   "r"(b0), "r"(b1))

// ---------------------------------------------------------------------------
// Kernel 0 (fused prep): blocks [0, NCONV_BLK): X fp32 -> fp16
//                        blocks [NCONV_BLK, +NFOLD_BLK): LoRA-fold W -> fp16
// ---------------------------------------------------------------------------
__global__ void prep(const float4* __restrict__ X,
                     const float* __restrict__ W,
                     const float* __restrict__ Aq, const float* __restrict__ Bq,
                     const float* __restrict__ Av, const float* __restrict__ Bv,
                     const float* __restrict__ s0p) {
    if (blockIdx.x < NCONV_BLK) {
        size_t i = (size_t)blockIdx.x * blockDim.x + threadIdx.x;
        float4 v = X[i];
        __half2* ph = reinterpret_cast<__half2*>(g_X) + i * 2;
        ph[0] = __floats2half2_rn(v.x, v.y);
        ph[1] = __floats2half2_rn(v.z, v.w);
    } else {
        int idx = (blockIdx.x - NCONV_BLK) * blockDim.x + threadIdx.x;
        if (idx >= ND * DD) return;
        int e = idx / DD;
        int d = idx - e * DD;
        float v = W[idx];
        float s = s0p[0];
        if (e < DD) {
            float acc = 0.f;
#pragma unroll
            for (int r = 0; r < RR; r++) acc = fmaf(Bq[e * RR + r], Aq[r * DD + d], acc);
            v = fmaf(s, acc, v);
        } else if (e >= 2 * DD) {
            int e2 = e - 2 * DD;
            float acc = 0.f;
#pragma unroll
            for (int r = 0; r < RR; r++) acc = fmaf(Bv[e2 * RR + r], Av[r * DD + d], acc);
            v = fmaf(s, acc, v);
        }
        g_W[idx] = __float2half(v);
    }
}

// ---------------------------------------------------------------------------
// Kernel 1: fp16 mma.sync GEMM, single term, fp32 accumulate.
//   Out[M, ND] = X @ W^T + bias
//   128x128x32 CTA tile, 8 warps (2x4), 64x32 warp tile, 4-stage cp.async.
//   ONE barrier per k-chunk; cp.async issued under the kk0 LDSM shadow.
//   2 CTAs/SM (80 KB smem each).
// ---------------------------------------------------------------------------
__global__ void __launch_bounds__(256, 2) gemm_mma(
    const float* __restrict__ bias, float* __restrict__ Out) {
    extern __shared__ char smem[];
    const uint32_t sb = smem_u32(smem);

    const int tid  = threadIdx.x;
    const int wid  = tid >> 5;
    const int lane = tid & 31;
    const int wm   = wid >> 2;          // 0..1  (64 rows each)
    const int wn   = wid & 3;           // 0..3  (32 cols each)
    const int n0   = blockIdx.x * BN;
    const int m0   = blockIdx.y * BM;

    // global load mapping: 512 16B chunks per matrix tile, 2 per thread
    const int r0c = tid >> 2;           // row for chunk 0 (0..63)
    const int cc  = tid & 3;            // 16B column (0..3)

    float acc[4][4][4];
#pragma unroll
    for (int i = 0; i < 4; i++)
#pragma unroll
        for (int j = 0; j < 4; j++)
#pragma unroll
            for (int q = 0; q < 4; q++) acc[i][j][q] = 0.f;

    // ---- stage loader ----
    auto load_stage = [&](int kt, int buf) {
        const uint32_t st = sb + buf * STG;
#pragma unroll
        for (int i = 0; i < 2; i++) {
            const int row = r0c + i * 64;
            const uint32_t so = st + row * ROWB + cc * 16;
            const size_t ga = (size_t)(m0 + row) * DD + kt * BK + cc * 8;
            const size_t gb = (size_t)(n0 + row) * DD + kt * BK + cc * 8;
            CPA(so + A_T, (const char*)(g_X + ga));
            CPA(so + B_T, (const char*)(g_W + gb));
        }
    };

    load_stage(0, 0); CP_COMMIT();
    load_stage(1, 1); CP_COMMIT();
    load_stage(2, 2); CP_COMMIT();

    // per-lane ldmatrix address pieces
    const int lrow = lane & 15;
    const int lhal = (lane >> 4) << 4;  // 0 or 16 bytes (8-col half)

    for (int kt = 0; kt < NKT; kt++) {
        const int buf = kt % STAGES;
        CP_WAIT2();
        __syncthreads();        // single barrier per k-chunk:
                                //  - makes stage `buf` visible to all warps
                                //  - all warps are past iteration kt-1 reads,
                                //    so writing buf (kt+3)%4 below is safe

        const uint32_t st = sb + buf * STG;
        const uint32_t abase = st + (wm * 64 + lrow) * ROWB + lhal;
        const uint32_t bbase = st + (wn * 32 + lrow) * ROWB + lhal;

        // ---- kk = 0: issue LDSM, then next-stage loads under their shadow ---
        uint32_t aw[4][4], bw[2][4];
#pragma unroll
        for (int ti = 0; ti < 4; ti++)
            LDSM4(aw[ti], abase + A_T + ti * (16 * ROWB));
#pragma unroll
        for (int tj = 0; tj < 2; tj++)
            LDSM4(bw[tj], bbase + B_T + tj * (16 * ROWB));

        if (kt + 3 < NKT) load_stage(kt + 3, (kt + 3) % STAGES);
        CP_COMMIT();

#pragma unroll
        for (int ti = 0; ti < 4; ti++) {
#pragma unroll
            for (int nj = 0; nj < 4; nj++) {
                const int tj = nj >> 1, o = nj & 1;
                MMA(acc[ti][nj], aw[ti], bw[tj][o], bw[tj][o + 2]);
            }
        }

        // ---- kk = 1: LDSM overlaps kk0 MMA drain -------------------------
#pragma unroll
        for (int ti = 0; ti < 4; ti++)
            LDSM4(aw[ti], abase + A_T + ti * (16 * ROWB) + 32);
#pragma unroll
        for (int tj = 0; tj < 2; tj++)
            LDSM4(bw[tj], bbase + B_T + tj * (16 * ROWB) + 32);

#pragma unroll
        for (int ti = 0; ti < 4; ti++) {
#pragma unroll
            for (int nj = 0; nj < 4; nj++) {
                const int tj = nj >> 1, o = nj & 1;
                MMA(acc[ti][nj], aw[ti], bw[tj][o], bw[tj][o + 2]);
            }
        }
        // no bottom barrier
    }

    // ---- epilogue: bias + store ----
    const int orow_base = m0 + wm * 64 + (lane >> 2);
    const int ocol_base = n0 + wn * 32 + (lane & 3) * 2;
#pragma unroll
    for (int ti = 0; ti < 4; ti++) {
        const int r0 = orow_base + ti * 16;
#pragma unroll
        for (int nj = 0; nj < 4; nj++) {
            const int c = ocol_base + nj * 8;
            const float2 bs = *reinterpret_cast<const float2*>(bias + c);
            float2 v0, v1;
            v0.x = acc[ti][nj][0] + bs.x;
            v0.y = acc[ti][nj][1] + bs.y;
            v1.x = acc[ti][nj][2] + bs.x;
            v1.y = acc[ti][nj][3] + bs.y;
            *reinterpret_cast<float2*>(Out + (size_t)r0 * ND + c) = v0;
            *reinterpret_cast<float2*>(Out + (size_t)(r0 + 8) * ND + c) = v1;
        }
    }
}

// ---------------------------------------------------------------------------
// Launch.  Inputs (metadata order): x, W_qkv, b_qkv, A_q, B_q, A_v, B_v, s0
// ---------------------------------------------------------------------------
extern "C" void kernel_launch(void* const* d_in, const int* in_sizes, int n_in,
                              void* d_out, int out_size) {
    const float* x  = (const float*)d_in[0];
    const float* W  = (const float*)d_in[1];
    const float* b  = (const float*)d_in[2];
    const float* Aq = (const float*)d_in[3];
    const float* Bq = (const float*)d_in[4];
    const float* Av = (const float*)d_in[5];
    const float* Bv = (const float*)d_in[6];
    const float* s0 = (const float*)d_in[7];
    float* out = (float*)d_out;

    prep<<<NCONV_BLK + NFOLD_BLK, 256>>>((const float4*)x, W, Aq, Bq, Av, Bv, s0);

    static bool attr_set = false;
    if (!attr_set) {
        cudaFuncSetAttribute(gemm_mma,
                             cudaFuncAttributeMaxDynamicSharedMemorySize,
                             SMEM_TOTAL);
        attr_set = true;
    }
    dim3 grid(ND / BN, MTOT / BM);      // (18, 512); x-fast => X tile L2 reuse
    gemm_mma<<<grid, 256, SMEM_TOTAL>>>(b, out);
}